// round 4
// baseline (speedup 1.0000x reference)
#include <cuda_runtime.h>
#include <cstdint>

#define N_NODES 100000
#define N_EDGES 3200000

// Scratch accumulator [N_NODES, 16], initialized to x (folds the (1+eps)*x term).
__device__ __align__(16) float g_aggr[N_NODES * 16];

// 1 if edge_index is int64, 0 if int32. Written by probe_kernel each call.
__device__ int g_idx_is_64;

// ---------------------------------------------------------------------------
// Kernel 0: probe edge_index dtype.
// int32 data viewed as int64 yields values with a nonzero hi word almost
// surely (hi word = another random index in [0,100000)), so "all 64 probes
// in range" <=> genuinely int64.
// ---------------------------------------------------------------------------
__global__ void probe_kernel(const long long* __restrict__ ei) {
    if (threadIdx.x == 0 && blockIdx.x == 0) {
        int ok64 = 1;
        for (int i = 0; i < 64; i++) {
            long long v = ei[i];
            if (v < 0 || v >= N_NODES) { ok64 = 0; break; }
        }
        g_idx_is_64 = ok64;
    }
}

// ---------------------------------------------------------------------------
// Kernel 1: aggr = x
// ---------------------------------------------------------------------------
__global__ void init_aggr_kernel(const float4* __restrict__ x) {
    int i = blockIdx.x * blockDim.x + threadIdx.x;
    const int n4 = N_NODES * 16 / 4;
    if (i < n4) {
        reinterpret_cast<float4*>(g_aggr)[i] = x[i];
    }
}

// ---------------------------------------------------------------------------
// Kernel 2: per-edge message + vectorized reduction into aggr
//   emb = lin1_w @ edge_attr[e] + lin1_b          (8 -> 16)
//   msg = relu(x[src] + emb)
//   aggr[dst] += msg     via red.global.add.v4.f32 (4 per edge)
// ---------------------------------------------------------------------------
__device__ __forceinline__ void red_add_v4(float* gptr, float a, float b, float c, float d) {
    asm volatile("red.global.add.v4.f32 [%0], {%1, %2, %3, %4};"
                 :: "l"(gptr), "f"(a), "f"(b), "f"(c), "f"(d)
                 : "memory");
}

__global__ void __launch_bounds__(256) edge_kernel(
    const float* __restrict__ x,
    const void* __restrict__ edge_index,       // [2, E] int32 or int64
    const float* __restrict__ edge_attr,       // [E, 8]
    const float* __restrict__ lin1_w,          // [16, 8]
    const float* __restrict__ lin1_b)          // [16]
{
    __shared__ float sw[128];
    __shared__ float sb[16];
    if (threadIdx.x < 128) sw[threadIdx.x] = lin1_w[threadIdx.x];
    if (threadIdx.x < 16)  sb[threadIdx.x] = lin1_b[threadIdx.x];
    __syncthreads();

    int e = blockIdx.x * blockDim.x + threadIdx.x;
    if (e >= N_EDGES) return;

    int src, dst;
    if (g_idx_is_64) {
        const long long* ei = (const long long*)edge_index;
        src = (int)ei[e];
        dst = (int)ei[(size_t)N_EDGES + e];
    } else {
        const int* ei = (const int*)edge_index;
        src = ei[e];
        dst = ei[N_EDGES + e];
    }
    // Defensive clamp: never generate an illegal address even on bad data.
    if ((unsigned)src >= N_NODES || (unsigned)dst >= N_NODES) return;

    // edge_attr row: 32B, two 16B loads
    const float4* ea = reinterpret_cast<const float4*>(edge_attr + (size_t)e * 8);
    float4 a0 = ea[0];
    float4 a1 = ea[1];

    // x[src] row: 64B, four 16B loads (L2-resident: x is only 6.4 MB)
    const float4* xs = reinterpret_cast<const float4*>(x + (size_t)src * 16);
    float4 x0 = __ldg(xs + 0);
    float4 x1 = __ldg(xs + 1);
    float4 x2 = __ldg(xs + 2);
    float4 x3 = __ldg(xs + 3);
    float xr[16] = {x0.x, x0.y, x0.z, x0.w, x1.x, x1.y, x1.z, x1.w,
                    x2.x, x2.y, x2.z, x2.w, x3.x, x3.y, x3.z, x3.w};

    float m[16];
#pragma unroll
    for (int k = 0; k < 16; k++) {
        const float* wk = sw + k * 8;
        float v = sb[k];
        v = fmaf(a0.x, wk[0], v);
        v = fmaf(a0.y, wk[1], v);
        v = fmaf(a0.z, wk[2], v);
        v = fmaf(a0.w, wk[3], v);
        v = fmaf(a1.x, wk[4], v);
        v = fmaf(a1.y, wk[5], v);
        v = fmaf(a1.z, wk[6], v);
        v = fmaf(a1.w, wk[7], v);
        v += xr[k];
        m[k] = fmaxf(v, 0.0f);
    }

    float* ag = g_aggr + (size_t)dst * 16;
    red_add_v4(ag + 0,  m[0],  m[1],  m[2],  m[3]);
    red_add_v4(ag + 4,  m[4],  m[5],  m[6],  m[7]);
    red_add_v4(ag + 8,  m[8],  m[9],  m[10], m[11]);
    red_add_v4(ag + 12, m[12], m[13], m[14], m[15]);
}

// ---------------------------------------------------------------------------
// Kernel 3: out[n] = aggr[n] @ nn_w.T + nn_b      (16 -> 32)
// (aggr already contains x + sum(msg))
// ---------------------------------------------------------------------------
__global__ void __launch_bounds__(256) node_kernel(
    const float* __restrict__ nn_w,   // [32, 16]
    const float* __restrict__ nn_b,   // [32]
    float* __restrict__ out)          // [N, 32]
{
    __shared__ float sw[512];
    __shared__ float sb[32];
    for (int i = threadIdx.x; i < 512; i += blockDim.x) sw[i] = nn_w[i];
    if (threadIdx.x < 32) sb[threadIdx.x] = nn_b[threadIdx.x];
    __syncthreads();

    int n = blockIdx.x * blockDim.x + threadIdx.x;
    if (n >= N_NODES) return;

    const float4* ar = reinterpret_cast<const float4*>(g_aggr + (size_t)n * 16);
    float4 v0 = ar[0], v1 = ar[1], v2 = ar[2], v3 = ar[3];
    float in[16] = {v0.x, v0.y, v0.z, v0.w, v1.x, v1.y, v1.z, v1.w,
                    v2.x, v2.y, v2.z, v2.w, v3.x, v3.y, v3.z, v3.w};

    float* orow = out + (size_t)n * 32;
#pragma unroll
    for (int j = 0; j < 32; j += 4) {
        float4 o;
        float* op = &o.x;
#pragma unroll
        for (int jj = 0; jj < 4; jj++) {
            const float* wj = sw + (j + jj) * 16;
            float acc = sb[j + jj];
#pragma unroll
            for (int k = 0; k < 16; k++) acc = fmaf(in[k], wj[k], acc);
            op[jj] = acc;
        }
        *reinterpret_cast<float4*>(orow + j) = o;
    }
}

// ---------------------------------------------------------------------------
extern "C" void kernel_launch(void* const* d_in, const int* in_sizes, int n_in,
                              void* d_out, int out_size) {
    const float* x          = (const float*)d_in[0];
    const void*  edge_index = d_in[1];
    const float* edge_attr  = (const float*)d_in[2];
    const float* lin1_w     = (const float*)d_in[3];
    const float* lin1_b     = (const float*)d_in[4];
    const float* nn_w       = (const float*)d_in[5];
    const float* nn_b       = (const float*)d_in[6];
    float*       out        = (float*)d_out;

    // 0) dtype probe (1 thread; trivially cheap)
    probe_kernel<<<1, 32>>>((const long long*)edge_index);

    // 1) aggr = x
    {
        int n4 = N_NODES * 16 / 4;
        int threads = 256;
        int blocks = (n4 + threads - 1) / threads;
        init_aggr_kernel<<<blocks, threads>>>(reinterpret_cast<const float4*>(x));
    }
    // 2) edge messages + reductions
    {
        int threads = 256;
        int blocks = (N_EDGES + threads - 1) / threads;
        edge_kernel<<<blocks, threads>>>(x, edge_index, edge_attr, lin1_w, lin1_b);
    }
    // 3) node update
    {
        int threads = 256;
        int blocks = (N_NODES + threads - 1) / threads;
        node_kernel<<<blocks, threads>>>(nn_w, nn_b, out);
    }
}